// round 6
// baseline (speedup 1.0000x reference)
#include <cuda_runtime.h>
#include <cuda_bf16.h>
#include <cstdint>

// CRF log-likelihood: B=256, M=1024, D=128, N=26.
//   1) emis_hmma     : e = X @ W^T via mma.sync m16n8k16 bf16 (sm_80 PTX —
//                      tcgen05 is unavailable: harness targets sm_103 w/o 'a')
//   2) scan2         : fused forward+adjoint scan, one warp per sequence
//   3) score_combine : unnormalized score + dot(v,u)
//   4) reduce_kernel : mean -> d_out[0]

#define B_ 256
#define M_ 1024
#define D_ 128
#define N_ 26
#define EST 32                          // padded emission row stride (f32)
#define FULLM 0xffffffffu
#define XS 136                          // bf16 row stride in smem (272B = 17*16B)
#define CS 36                           // f32 row stride for C rebuffer

__device__ float g_e[(size_t)B_ * M_ * EST];  // 33.5 MB padded emissions
__device__ float g_midv[B_ * 32];
__device__ float g_midu[B_ * 32];
__device__ float g_cfw[B_];
__device__ float g_cbw[B_];
__device__ float g_res[B_];

// pack two f32 -> bf16x2 (lo = x, hi = y)
__device__ __forceinline__ uint32_t bf2(float x, float y) {
    uint32_t p;
    asm("cvt.rn.bf16x2.f32 %0, %1, %2;" : "=r"(p) : "f"(y), "f"(x));
    return p;
}

__device__ __forceinline__ void mma_bf16(float* d, const uint32_t* a,
                                         const uint32_t* b) {
    asm volatile(
        "mma.sync.aligned.m16n8k16.row.col.f32.bf16.bf16.f32 "
        "{%0,%1,%2,%3}, {%4,%5,%6,%7}, {%8,%9}, {%0,%1,%2,%3};"
        : "+f"(d[0]), "+f"(d[1]), "+f"(d[2]), "+f"(d[3])
        : "r"(a[0]), "r"(a[1]), "r"(a[2]), "r"(a[3]), "r"(b[0]), "r"(b[1]));
}

// ---------------------------------------------------------------------------
// Kernel 1: e = X @ W^T via HMMA bf16.
//   Block 128 thr (4 warps); each warp: 4 tiles of 32 rows x 32 labels.
//   W (bf16, rows 26..31 zero) staged once per block; X tile staged per warp
//   (coalesced LDG.128 -> cvt -> STS.64, stride-136 pad = conflict-free
//   fragment LDS.32).  C rebuffered through smem for coalesced STG.128.
// ---------------------------------------------------------------------------
__global__ __launch_bounds__(128) void emis_hmma(const float* __restrict__ X,
                                                 const float* __restrict__ W) {
    __shared__ __nv_bfloat16 Wb[32 * XS];          //  8704 B
    __shared__ __nv_bfloat16 xs_all[4][32 * XS];   // 34816 B

    const int tid  = threadIdx.x;
    const int w    = tid >> 5;
    const int lane = tid & 31;
    const int q    = lane & 3;          // threadID in group
    const int r8   = lane >> 2;         // group id

    // stage W -> Wb (bf16), zero rows >= 26
#pragma unroll
    for (int i = 0; i < 8; i++) {
        const int idx = tid + i * 128;          // 1024 float4 slots
        const int row = idx >> 5, c4 = idx & 31;
        float4 v = make_float4(0.f, 0.f, 0.f, 0.f);
        if (row < N_) v = __ldg((const float4*)(W + row * D_) + c4);
        uint2 p = make_uint2(bf2(v.x, v.y), bf2(v.z, v.w));
        *(uint2*)&Wb[row * XS + c4 * 4] = p;
    }
    __syncthreads();

    __nv_bfloat16* xw = xs_all[w];
    float* csm = (float*)xw;            // C rebuffer aliases xs (phase-separated)

    for (int l = 0; l < 4; l++) {
        const size_t rowbase = (size_t)blockIdx.x * 512 + l * 128 + w * 32;

        // stage X tile: 32 rows x 128 f32 -> bf16 smem
#pragma unroll
        for (int i = 0; i < 32; i++) {
            float4 v = __ldg((const float4*)(X + (rowbase + i) * D_) + lane);
            uint2 p = make_uint2(bf2(v.x, v.y), bf2(v.z, v.w));
            *(uint2*)&xs_all[w][i * XS + lane * 4] = p;
        }
        __syncwarp();

        float acc[2][4][4];
#pragma unroll
        for (int mt = 0; mt < 2; mt++)
#pragma unroll
            for (int nt = 0; nt < 4; nt++)
#pragma unroll
                for (int e = 0; e < 4; e++) acc[mt][nt][e] = 0.f;

#pragma unroll
        for (int ks = 0; ks < 8; ks++) {
            const int k0 = ks * 16;
            uint32_t afrag[2][4], bfrag[4][2];
#pragma unroll
            for (int mt = 0; mt < 2; mt++) {
                const int row = mt * 16 + r8;
                afrag[mt][0] = *(const uint32_t*)&xw[row * XS + k0 + 2 * q];
                afrag[mt][1] = *(const uint32_t*)&xw[(row + 8) * XS + k0 + 2 * q];
                afrag[mt][2] = *(const uint32_t*)&xw[row * XS + k0 + 8 + 2 * q];
                afrag[mt][3] = *(const uint32_t*)&xw[(row + 8) * XS + k0 + 8 + 2 * q];
            }
#pragma unroll
            for (int nt = 0; nt < 4; nt++) {
                const int n = nt * 8 + r8;
                bfrag[nt][0] = *(const uint32_t*)&Wb[n * XS + k0 + 2 * q];
                bfrag[nt][1] = *(const uint32_t*)&Wb[n * XS + k0 + 8 + 2 * q];
            }
#pragma unroll
            for (int mt = 0; mt < 2; mt++)
#pragma unroll
                for (int nt = 0; nt < 4; nt++)
                    mma_bf16(acc[mt][nt], afrag[mt], bfrag[nt]);
        }
        __syncwarp();

        // rebuffer C into smem (stride CS), then coalesced STG.128
#pragma unroll
        for (int mt = 0; mt < 2; mt++)
#pragma unroll
            for (int nt = 0; nt < 4; nt++) {
                const int rl = mt * 16 + r8;
                const int c  = nt * 8 + 2 * q;
                *(float2*)&csm[rl * CS + c] =
                    make_float2(acc[mt][nt][0], acc[mt][nt][1]);
                *(float2*)&csm[(rl + 8) * CS + c] =
                    make_float2(acc[mt][nt][2], acc[mt][nt][3]);
            }
        __syncwarp();
#pragma unroll
        for (int i = 0; i < 8; i++) {
            const int idx = lane + i * 32;      // 256 float4 slots
            const int row = idx >> 3, c4 = idx & 7;
            float4 o = *(const float4*)&csm[row * CS + c4 * 4];
            *(float4*)(g_e + (rowbase + row) * EST + c4 * 4) = o;
        }
        __syncwarp();
    }
}

// ---------------------------------------------------------------------------
// dot of broadcast state (7 float4, 26 valid) with per-lane ET coefficients
// ---------------------------------------------------------------------------
__device__ __forceinline__ float dot26(const float4 t[7], const float* ET) {
    float a0 = t[0].x * ET[0], a1 = t[0].y * ET[1];
    float a2 = t[0].z * ET[2], a3 = t[0].w * ET[3];
#pragma unroll
    for (int qq = 1; qq < 6; qq++) {
        a0 += t[qq].x * ET[qq * 4 + 0];
        a1 += t[qq].y * ET[qq * 4 + 1];
        a2 += t[qq].z * ET[qq * 4 + 2];
        a3 += t[qq].w * ET[qq * 4 + 3];
    }
    a0 += t[6].x * ET[24];
    a1 += t[6].y * ET[25];
    return (a0 + a1) + (a2 + a3);
}

// ---------------------------------------------------------------------------
// Kernel 2: fused forward+adjoint scan, one warp per sequence.
//   512 joint iterations t: fwd uses E_{t+1} (t<=510), bwd uses E_{1023-t}.
//   Both chains exchange state via double-buffered smem (one syncwarp/step).
// ---------------------------------------------------------------------------
__global__ __launch_bounds__(32) void scan2(const float* __restrict__ Tg) {
    __shared__ __align__(16) float fbuf[2][32];
    __shared__ __align__(16) float bbuf[2][32];

    const int seq  = blockIdx.x;
    const int lane = threadIdx.x;
    const bool act = lane < N_;
    const float* er = g_e + (size_t)seq * M_ * EST;

    float ETc[26], ETr[26];
#pragma unroll
    for (int b = 0; b < 26; b++) {
        ETc[b] = act ? __expf(__ldg(Tg + b * 26 + lane)) : 0.f;   // col of expT
        ETr[b] = act ? __expf(__ldg(Tg + lane * 26 + b)) : 0.f;   // row of expT
    }

    float v = act ? __expf(__ldg(er + lane)) : 0.f;               // v_0
    float u = 1.f;
    float Cf = 0.f, Cb = 0.f;

    float ebF[8], ebB[8];
#pragma unroll
    for (int i = 0; i < 8; i++) {
        ebF[i] = act ? __ldg(er + (size_t)(1 + i) * EST + lane) : 0.f;
        ebB[i] = act ? __ldg(er + (size_t)(1023 - i) * EST + lane) : 0.f;
    }
    float EcF = __expf(ebF[0]);          // E_1
    float EcB = __expf(ebB[0]);          // E_1023

    if (act) { fbuf[0][lane] = v; bbuf[0][lane] = EcB; }          // s_1023
    __syncwarp();

    int t = 0;
    for (int blk = 0; blk < 63; blk++) {         // t = 0..503
#pragma unroll
        for (int j = 0; j < 8; j++) {
            float EnF = __expf(ebF[(j + 1) & 7]);
            float EnB = __expf(ebB[(j + 1) & 7]);

            float4 tF[7], tB[7];
            const float4* fp = (const float4*)&fbuf[j & 1][0];
            const float4* bp = (const float4*)&bbuf[j & 1][0];
#pragma unroll
            for (int qq = 0; qq < 7; qq++) { tF[qq] = fp[qq]; tB[qq] = bp[qq]; }

            v = EcF * dot26(tF, ETc);  EcF = EnF;
            u = dot26(tB, ETr);        EcB = EnB;

            if (j == 7) {
                int exf = (__float_as_int(tF[0].x) >> 23) - 127;
                int exb = (__float_as_int(tB[0].x) >> 23) - 127;
                Cf += (float)exf;  Cb += (float)exb;
                if (act) {
                    v = __int_as_float(__float_as_int(v) - (exf << 23));
                    u = __int_as_float(__float_as_int(u) - (exb << 23));
                }
            }

            if (t + 9 <= 511)
                ebF[j] = act ? __ldg(er + (size_t)(t + 9) * EST + lane) : 0.f;
            if (t <= 503)
                ebB[j] = act ? __ldg(er + (size_t)(1015 - t) * EST + lane) : 0.f;

            if (act) { fbuf[(j + 1) & 1][lane] = v; bbuf[(j + 1) & 1][lane] = EcB * u; }
            __syncwarp();
            t++;
        }
    }
    // tail: t = 504..511 — fwd active j=0..6 (t<=510), bwd all 8; no renorm
#pragma unroll
    for (int j = 0; j < 8; j++) {
        float EnF = (j < 7) ? __expf(ebF[(j + 1) & 7]) : 1.f;
        float EnB = (j < 7) ? __expf(ebB[(j + 1) & 7]) : 1.f;

        float4 tF[7], tB[7];
        const float4* fp = (const float4*)&fbuf[j & 1][0];
        const float4* bp = (const float4*)&bbuf[j & 1][0];
#pragma unroll
        for (int qq = 0; qq < 7; qq++) { tF[qq] = fp[qq]; tB[qq] = bp[qq]; }

        if (j < 7) { v = EcF * dot26(tF, ETc); EcF = EnF; }
        u = dot26(tB, ETr);  EcB = EnB;

        if (act) { fbuf[(j + 1) & 1][lane] = v; bbuf[(j + 1) & 1][lane] = EcB * u; }
        __syncwarp();
    }

    if (act) { g_midv[seq * 32 + lane] = v; g_midu[seq * 32 + lane] = u; }
    if (lane == 0) { g_cfw[seq] = Cf; g_cbw[seq] = Cb; }
}

// ---------------------------------------------------------------------------
// Kernel 3: unnormalized score + combine halves
// ---------------------------------------------------------------------------
__global__ __launch_bounds__(32) void score_combine(const int* __restrict__ labels,
                                                    const float* __restrict__ Tg) {
    const int seq  = blockIdx.x;
    const int lane = threadIdx.x;
    const float* er = g_e + (size_t)seq * M_ * EST;
    const int*  lab = labels + seq * M_;

    float pv = (lane < N_) ? g_midv[seq * 32 + lane] * g_midu[seq * 32 + lane] : 0.f;
#pragma unroll
    for (int off = 16; off; off >>= 1) pv += __shfl_xor_sync(FULLM, pv, off);

    int y[32];
    {
        const int4* lp = (const int4*)(lab + lane * 32);
#pragma unroll
        for (int i = 0; i < 8; i++) {
            int4 qd = __ldg(lp + i);
            y[i * 4] = qd.x; y[i * 4 + 1] = qd.y; y[i * 4 + 2] = qd.z; y[i * 4 + 3] = qd.w;
        }
    }
    int y_next0 = __shfl_down_sync(FULLM, y[0], 1);

    float se = 0.f, st = 0.f;
#pragma unroll
    for (int i = 0; i < 32; i++) {
        const int m = lane * 32 + i;
        se += __ldg(er + (size_t)m * EST + y[i]);
        const int yn = (i < 31) ? y[i + 1] : y_next0;
        if (m < 1023) st += __ldg(Tg + y[i] * 26 + yn);
    }
    float sc = se + st;
#pragma unroll
    for (int off = 16; off; off >>= 1) sc += __shfl_xor_sync(FULLM, sc, off);

    if (lane == 0) {
        const float LN2 = 0.6931471805599453f;
        float logZ = (g_cfw[seq] + g_cbw[seq]) * LN2 + __logf(pv);
        g_res[seq] = sc - logZ;
    }
}

// ---------------------------------------------------------------------------
// Kernel 4: mean -> d_out[0]
// ---------------------------------------------------------------------------
__global__ __launch_bounds__(256) void reduce_kernel(float* __restrict__ out) {
    const int tid = threadIdx.x;
    float val = g_res[tid];
#pragma unroll
    for (int off = 16; off; off >>= 1) val += __shfl_xor_sync(FULLM, val, off);

    __shared__ float sh[8];
    if ((tid & 31) == 0) sh[tid >> 5] = val;
    __syncthreads();
    if (tid < 8) {
        float t = sh[tid];
#pragma unroll
        for (int off = 4; off; off >>= 1) t += __shfl_xor_sync(0xffu, t, off);
        if (tid == 0) out[0] = t * (1.0f / 256.0f);
    }
}

// ---------------------------------------------------------------------------
extern "C" void kernel_launch(void* const* d_in, const int* in_sizes, int n_in,
                              void* d_out, int out_size) {
    const float* X      = (const float*)d_in[0];   // [256,1024,128] f32
    const int*   labels = (const int*)d_in[1];     // [256,1024] i32
    const float* W      = (const float*)d_in[2];   // [26,128] f32
    const float* Tm     = (const float*)d_in[3];   // [26,26] f32

    emis_hmma<<<512, 128>>>(X, W);
    scan2<<<B_, 32>>>(Tm);
    score_combine<<<B_, 32>>>(labels, Tm);
    reduce_kernel<<<1, 256>>>((float*)d_out);
}

// round 7
// speedup vs baseline: 1.5675x; 1.5675x over previous
#include <cuda_runtime.h>
#include <cuda_bf16.h>
#include <cstdint>

// CRF log-likelihood: B=256, M=1024, D=128, N=26.
//   1) emis_hmma     : e = X @ W^T via mma.sync m16n8k16 bf16 (unchanged R6)
//   2) scan_kernel   : SPLIT forward/adjoint scan (reverted to R4 structure —
//                      one chain per 32-thread block, 512 blocks)
//   3) score_combine : unnormalized score + dot(v,u)
//   4) reduce_kernel : mean -> d_out[0]

#define B_ 256
#define M_ 1024
#define D_ 128
#define N_ 26
#define EST 32                          // padded emission row stride (f32)
#define FULLM 0xffffffffu
#define XS 136                          // bf16 row stride in smem
#define CS 36                           // f32 row stride for C rebuffer

__device__ float g_e[(size_t)B_ * M_ * EST];  // 33.5 MB padded emissions
__device__ float g_midv[B_ * 32];
__device__ float g_midu[B_ * 32];
__device__ float g_cfw[B_];
__device__ float g_cbw[B_];
__device__ float g_res[B_];

__device__ __forceinline__ uint32_t bf2(float x, float y) {
    uint32_t p;
    asm("cvt.rn.bf16x2.f32 %0, %1, %2;" : "=r"(p) : "f"(y), "f"(x));
    return p;
}

__device__ __forceinline__ void mma_bf16(float* d, const uint32_t* a,
                                         const uint32_t* b) {
    asm volatile(
        "mma.sync.aligned.m16n8k16.row.col.f32.bf16.bf16.f32 "
        "{%0,%1,%2,%3}, {%4,%5,%6,%7}, {%8,%9}, {%0,%1,%2,%3};"
        : "+f"(d[0]), "+f"(d[1]), "+f"(d[2]), "+f"(d[3])
        : "r"(a[0]), "r"(a[1]), "r"(a[2]), "r"(a[3]), "r"(b[0]), "r"(b[1]));
}

// ---------------------------------------------------------------------------
// Kernel 1: e = X @ W^T via HMMA bf16 (identical to R6)
// ---------------------------------------------------------------------------
__global__ __launch_bounds__(128) void emis_hmma(const float* __restrict__ X,
                                                 const float* __restrict__ W) {
    __shared__ __nv_bfloat16 Wb[32 * XS];
    __shared__ __nv_bfloat16 xs_all[4][32 * XS];

    const int tid  = threadIdx.x;
    const int w    = tid >> 5;
    const int lane = tid & 31;
    const int q    = lane & 3;
    const int r8   = lane >> 2;

#pragma unroll
    for (int i = 0; i < 8; i++) {
        const int idx = tid + i * 128;
        const int row = idx >> 5, c4 = idx & 31;
        float4 v = make_float4(0.f, 0.f, 0.f, 0.f);
        if (row < N_) v = __ldg((const float4*)(W + row * D_) + c4);
        uint2 p = make_uint2(bf2(v.x, v.y), bf2(v.z, v.w));
        *(uint2*)&Wb[row * XS + c4 * 4] = p;
    }
    __syncthreads();

    __nv_bfloat16* xw = xs_all[w];
    float* csm = (float*)xw;

    for (int l = 0; l < 4; l++) {
        const size_t rowbase = (size_t)blockIdx.x * 512 + l * 128 + w * 32;

#pragma unroll
        for (int i = 0; i < 32; i++) {
            float4 v = __ldg((const float4*)(X + (rowbase + i) * D_) + lane);
            uint2 p = make_uint2(bf2(v.x, v.y), bf2(v.z, v.w));
            *(uint2*)&xs_all[w][i * XS + lane * 4] = p;
        }
        __syncwarp();

        float acc[2][4][4];
#pragma unroll
        for (int mt = 0; mt < 2; mt++)
#pragma unroll
            for (int nt = 0; nt < 4; nt++)
#pragma unroll
                for (int e = 0; e < 4; e++) acc[mt][nt][e] = 0.f;

#pragma unroll
        for (int ks = 0; ks < 8; ks++) {
            const int k0 = ks * 16;
            uint32_t afrag[2][4], bfrag[4][2];
#pragma unroll
            for (int mt = 0; mt < 2; mt++) {
                const int row = mt * 16 + r8;
                afrag[mt][0] = *(const uint32_t*)&xw[row * XS + k0 + 2 * q];
                afrag[mt][1] = *(const uint32_t*)&xw[(row + 8) * XS + k0 + 2 * q];
                afrag[mt][2] = *(const uint32_t*)&xw[row * XS + k0 + 8 + 2 * q];
                afrag[mt][3] = *(const uint32_t*)&xw[(row + 8) * XS + k0 + 8 + 2 * q];
            }
#pragma unroll
            for (int nt = 0; nt < 4; nt++) {
                const int n = nt * 8 + r8;
                bfrag[nt][0] = *(const uint32_t*)&Wb[n * XS + k0 + 2 * q];
                bfrag[nt][1] = *(const uint32_t*)&Wb[n * XS + k0 + 8 + 2 * q];
            }
#pragma unroll
            for (int mt = 0; mt < 2; mt++)
#pragma unroll
                for (int nt = 0; nt < 4; nt++)
                    mma_bf16(acc[mt][nt], afrag[mt], bfrag[nt]);
        }
        __syncwarp();

#pragma unroll
        for (int mt = 0; mt < 2; mt++)
#pragma unroll
            for (int nt = 0; nt < 4; nt++) {
                const int rl = mt * 16 + r8;
                const int c  = nt * 8 + 2 * q;
                *(float2*)&csm[rl * CS + c] =
                    make_float2(acc[mt][nt][0], acc[mt][nt][1]);
                *(float2*)&csm[(rl + 8) * CS + c] =
                    make_float2(acc[mt][nt][2], acc[mt][nt][3]);
            }
        __syncwarp();
#pragma unroll
        for (int i = 0; i < 8; i++) {
            const int idx = lane + i * 32;
            const int row = idx >> 3, c4 = idx & 7;
            float4 o = *(const float4*)&csm[row * CS + c4 * 4];
            *(float4*)(g_e + (rowbase + row) * EST + c4 * 4) = o;
        }
        __syncwarp();
    }
}

// ---------------------------------------------------------------------------
__device__ __forceinline__ float dot26(const float4 t[7], const float* ET) {
    float a0 = t[0].x * ET[0], a1 = t[0].y * ET[1];
    float a2 = t[0].z * ET[2], a3 = t[0].w * ET[3];
#pragma unroll
    for (int qq = 1; qq < 6; qq++) {
        a0 += t[qq].x * ET[qq * 4 + 0];
        a1 += t[qq].y * ET[qq * 4 + 1];
        a2 += t[qq].z * ET[qq * 4 + 2];
        a3 += t[qq].w * ET[qq * 4 + 3];
    }
    a0 += t[6].x * ET[24];
    a1 += t[6].y * ET[25];
    return (a0 + a1) + (a2 + a3);
}

// ---------------------------------------------------------------------------
// Kernel 2: SPLIT scan (R4 structure). even block -> forward, odd -> adjoint.
// ---------------------------------------------------------------------------
__global__ __launch_bounds__(32) void scan_kernel(const float* __restrict__ Tg) {
    __shared__ __align__(16) float vbuf[2][32];

    const int seq  = blockIdx.x >> 1;
    const int bwd  = blockIdx.x & 1;
    const int lane = threadIdx.x;
    const bool act = lane < N_;
    const float* er = g_e + (size_t)seq * M_ * EST;

    float Cl2 = 0.f;

    if (!bwd) {
        float ETc[26];
#pragma unroll
        for (int b = 0; b < 26; b++)
            ETc[b] = act ? __expf(__ldg(Tg + b * 26 + lane)) : 0.f;

        float v = act ? __expf(__ldg(er + lane)) : 0.f;

        float ebuf[8];
#pragma unroll
        for (int i = 0; i < 8; i++)
            ebuf[i] = act ? __ldg(er + (size_t)(1 + i) * EST + lane) : 0.f;
        float Ecur = __expf(ebuf[0]);

        if (act) vbuf[0][lane] = v;
        __syncwarp();

        int m = 1;
        for (int blk = 0; blk < 63; blk++) {
#pragma unroll
            for (int j = 0; j < 8; j++) {
                float Enext = __expf(ebuf[(j + 1) & 7]);
                float4 t[7];
                const float4* vp = (const float4*)&vbuf[j & 1][0];
#pragma unroll
                for (int qq = 0; qq < 7; qq++) t[qq] = vp[qq];
                v = Ecur * dot26(t, ETc);
                Ecur = Enext;
                if (j == 7) {
                    int ex = (__float_as_int(t[0].x) >> 23) - 127;
                    Cl2 += (float)ex;
                    if (act) v = __int_as_float(__float_as_int(v) - (ex << 23));
                }
                const int mn = m + 8;
                if (mn <= 511)
                    ebuf[j] = act ? __ldg(er + (size_t)mn * EST + lane) : 0.f;
                if (act) vbuf[(j + 1) & 1][lane] = v;
                __syncwarp();
                m++;
            }
        }
#pragma unroll
        for (int j = 0; j < 7; j++) {
            float Enext = (j < 6) ? __expf(ebuf[j + 1]) : 1.f;
            float4 t[7];
            const float4* vp = (const float4*)&vbuf[j & 1][0];
#pragma unroll
            for (int qq = 0; qq < 7; qq++) t[qq] = vp[qq];
            v = Ecur * dot26(t, ETc);
            Ecur = Enext;
            if (act) vbuf[(j + 1) & 1][lane] = v;
            __syncwarp();
        }
        if (act) g_midv[seq * 32 + lane] = v;
        if (lane == 0) g_cfw[seq] = Cl2;
    } else {
        float ETr[26];
#pragma unroll
        for (int a = 0; a < 26; a++)
            ETr[a] = act ? __expf(__ldg(Tg + lane * 26 + a)) : 0.f;

        float u = act ? 1.f : 0.f;

        float ebuf[8];
#pragma unroll
        for (int i = 0; i < 8; i++)
            ebuf[i] = act ? __ldg(er + (size_t)(1023 - i) * EST + lane) : 0.f;
        float Ecur = __expf(ebuf[0]);

        if (act) vbuf[0][lane] = Ecur * u;
        __syncwarp();

        int k = 0;
        for (int blk = 0; blk < 64; blk++) {
#pragma unroll
            for (int j = 0; j < 8; j++) {
                float Enext = __expf(ebuf[(j + 1) & 7]);
                float4 t[7];
                const float4* vp = (const float4*)&vbuf[j & 1][0];
#pragma unroll
                for (int qq = 0; qq < 7; qq++) t[qq] = vp[qq];
                u = dot26(t, ETr);
                Ecur = Enext;
                if (j == 7) {
                    int ex = (__float_as_int(t[0].x) >> 23) - 127;
                    Cl2 += (float)ex;
                    if (act) u = __int_as_float(__float_as_int(u) - (ex << 23));
                }
                const int kn = k + 8;
                if (kn <= 511)
                    ebuf[j] = act ? __ldg(er + (size_t)(1023 - kn) * EST + lane) : 0.f;
                if (act) vbuf[(j + 1) & 1][lane] = Ecur * u;
                __syncwarp();
                k++;
            }
        }
        if (act) g_midu[seq * 32 + lane] = u;
        if (lane == 0) g_cbw[seq] = Cl2;
    }
}

// ---------------------------------------------------------------------------
// Kernel 3: unnormalized score + combine halves
// ---------------------------------------------------------------------------
__global__ __launch_bounds__(32) void score_combine(const int* __restrict__ labels,
                                                    const float* __restrict__ Tg) {
    const int seq  = blockIdx.x;
    const int lane = threadIdx.x;
    const float* er = g_e + (size_t)seq * M_ * EST;
    const int*  lab = labels + seq * M_;

    float pv = (lane < N_) ? g_midv[seq * 32 + lane] * g_midu[seq * 32 + lane] : 0.f;
#pragma unroll
    for (int off = 16; off; off >>= 1) pv += __shfl_xor_sync(FULLM, pv, off);

    int y[32];
    {
        const int4* lp = (const int4*)(lab + lane * 32);
#pragma unroll
        for (int i = 0; i < 8; i++) {
            int4 qd = __ldg(lp + i);
            y[i * 4] = qd.x; y[i * 4 + 1] = qd.y; y[i * 4 + 2] = qd.z; y[i * 4 + 3] = qd.w;
        }
    }
    int y_next0 = __shfl_down_sync(FULLM, y[0], 1);

    float se = 0.f, st = 0.f;
#pragma unroll
    for (int i = 0; i < 32; i++) {
        const int m = lane * 32 + i;
        se += __ldg(er + (size_t)m * EST + y[i]);
        const int yn = (i < 31) ? y[i + 1] : y_next0;
        if (m < 1023) st += __ldg(Tg + y[i] * 26 + yn);
    }
    float sc = se + st;
#pragma unroll
    for (int off = 16; off; off >>= 1) sc += __shfl_xor_sync(FULLM, sc, off);

    if (lane == 0) {
        const float LN2 = 0.6931471805599453f;
        float logZ = (g_cfw[seq] + g_cbw[seq]) * LN2 + __logf(pv);
        g_res[seq] = sc - logZ;
    }
}

// ---------------------------------------------------------------------------
// Kernel 4: mean -> d_out[0]
// ---------------------------------------------------------------------------
__global__ __launch_bounds__(256) void reduce_kernel(float* __restrict__ out) {
    const int tid = threadIdx.x;
    float val = g_res[tid];
#pragma unroll
    for (int off = 16; off; off >>= 1) val += __shfl_xor_sync(FULLM, val, off);

    __shared__ float sh[8];
    if ((tid & 31) == 0) sh[tid >> 5] = val;
    __syncthreads();
    if (tid < 8) {
        float t = sh[tid];
#pragma unroll
        for (int off = 4; off; off >>= 1) t += __shfl_xor_sync(0xffu, t, off);
        if (tid == 0) out[0] = t * (1.0f / 256.0f);
    }
}

// ---------------------------------------------------------------------------
extern "C" void kernel_launch(void* const* d_in, const int* in_sizes, int n_in,
                              void* d_out, int out_size) {
    const float* X      = (const float*)d_in[0];   // [256,1024,128] f32
    const int*   labels = (const int*)d_in[1];     // [256,1024] i32
    const float* W      = (const float*)d_in[2];   // [26,128] f32
    const float* Tm     = (const float*)d_in[3];   // [26,26] f32

    emis_hmma<<<512, 128>>>(X, W);
    scan_kernel<<<2 * B_, 32>>>(Tm);
    score_combine<<<B_, 32>>>(labels, Tm);
    reduce_kernel<<<1, 256>>>((float*)d_out);
}